// round 3
// baseline (speedup 1.0000x reference)
#include <cuda_runtime.h>
#include <cuda_bf16.h>
#include <cstdint>

// Problem shape (fixed by reference setup_inputs)
#define B_   16
#define C_   384
#define CR_  96
#define HW_  12544          // 112*112
#define HW4_ 3136           // HW/4 (float4 per plane); 3136 = 448*7 exactly
#define T_   448            // threads per CTA
#define K_   7              // float4 chunks per thread

// Device-global scratch & sync state (no allocations allowed).
__device__ float    g_mean[B_ * C_];
__device__ float    g_scale[B_ * C_];
__device__ unsigned g_ctr[B_];    // zero-init; reset to 0 by last CTA each use
__device__ unsigned g_flag[B_];   // monotone epoch per batch (graph-replay safe)

// ---------------------------------------------------------------------------
// Fused persistent SE kernel.
// Grid = 384 CTAs (one per channel), all co-resident (min 3 CTAs/SM enforced),
// looping over the 16 batches. x is read from DRAM exactly ONCE:
//   stage plane -> smem, mean -> global, last-CTA computes FC + releases flag,
//   others prefetch next batch while spinning, then scale smem plane -> out.
// ---------------------------------------------------------------------------
__global__ void __launch_bounds__(T_, 3)
se_fused_kernel(const float* __restrict__ x,
                const float* __restrict__ w1, const float* __restrict__ b1,
                const float* __restrict__ w2, const float* __restrict__ b2,
                float* __restrict__ out)
{
    extern __shared__ float4 sbuf[];       // HW4_ float4 = 50176 B (dynamic)
    __shared__ float s_mean[C_];
    __shared__ float s_t[CR_];
    __shared__ float s_warp[T_ / 32];
    __shared__ int   s_islast;

    const int tid  = threadIdx.x;
    const int lane = tid & 31;
    const int wid  = tid >> 5;
    const int cta  = blockIdx.x;           // channel index 0..383

    const float4* __restrict__ xb = reinterpret_cast<const float4*>(x)
                                    + (size_t)cta * HW4_;

    // Prefetch batch 0 plane into registers.
    float4 v[K_];
    #pragma unroll
    for (int k = 0; k < K_; k++)
        v[k] = __ldcs(xb + tid + k * T_);

    for (int b = 0; b < B_; b++) {
        const int plane = b * C_ + cta;

        // Read this batch's flag epoch BEFORE arriving (safe: bump can only
        // happen after all 384 CTAs arrive, which is after this read).
        unsigned start_epoch = 0u;
        if (tid == 0)
            start_epoch = *((volatile const unsigned*)&g_flag[b]);

        // Stage registers -> smem and accumulate partial sum.
        float sum = 0.0f;
        #pragma unroll
        for (int k = 0; k < K_; k++) {
            sbuf[k * T_ + tid] = v[k];
            sum += (v[k].x + v[k].y) + (v[k].z + v[k].w);
        }

        // CTA reduction (448 -> 1).
        #pragma unroll
        for (int o = 16; o > 0; o >>= 1)
            sum += __shfl_down_sync(0xffffffffu, sum, o);
        if (lane == 0) s_warp[wid] = sum;
        __syncthreads();
        if (wid == 0) {
            sum = (lane < T_ / 32) ? s_warp[lane] : 0.0f;
            #pragma unroll
            for (int o = 8; o > 0; o >>= 1)
                sum += __shfl_down_sync(0xffffffffu, sum, o);
            if (lane == 0) {
                g_mean[plane] = sum * (1.0f / (float)HW_);
                __threadfence();
                unsigned old = atomicAdd(&g_ctr[b], 1u);
                s_islast = (old == (unsigned)(C_ - 1));
            }
        }
        __syncthreads();

        if (s_islast) {
            // This CTA saw all means: compute the FC chain for batch b.
            if (tid < C_) s_mean[tid] = __ldcg(&g_mean[b * C_ + tid]);
            __syncthreads();
            if (tid < CR_) {
                float acc = b1[tid];
                const float* __restrict__ wr = w1 + tid * C_;
                #pragma unroll 16
                for (int c = 0; c < C_; c++)
                    acc = fmaf(s_mean[c], __ldg(&wr[c]), acc);
                s_t[tid] = fmaxf(acc, 0.0f);
            }
            __syncthreads();
            if (tid < C_) {
                float acc = b2[tid];
                const float* __restrict__ wc = w2 + tid * CR_;
                #pragma unroll 16
                for (int r = 0; r < CR_; r++)
                    acc = fmaf(s_t[r], __ldg(&wc[r]), acc);
                g_scale[b * C_ + tid] =
                    __saturatef(fmaf(acc, 1.0f / 6.0f, 0.5f));
            }
            __threadfence();
            __syncthreads();
            if (tid == 0) {
                g_ctr[b] = 0;                 // reset for next replay
                __threadfence();
                atomicAdd(&g_flag[b], 1u);    // release
            }
        }

        // Prefetch next batch's plane NOW — these DRAM reads fly while we
        // wait for the FC release, keeping HBM busy through the sync.
        if (b + 1 < B_) {
            const float4* __restrict__ pn = xb + (size_t)(b + 1) * C_ * HW4_;
            #pragma unroll
            for (int k = 0; k < K_; k++)
                v[k] = __ldcs(pn + tid + k * T_);
        }

        if (!s_islast) {
            if (tid == 0) {
                while (*((volatile const unsigned*)&g_flag[b]) == start_epoch)
                    __nanosleep(100);
            }
            __syncthreads();
        }

        // Scale the smem-resident plane and stream it out.
        const float sc = __ldcg(&g_scale[plane]);
        float4* __restrict__ o = reinterpret_cast<float4*>(out)
                                 + (size_t)plane * HW4_;
        #pragma unroll
        for (int k = 0; k < K_; k++) {
            float4 t = sbuf[k * T_ + tid];
            t.x *= sc; t.y *= sc; t.z *= sc; t.w *= sc;
            __stcs(o + tid + k * T_, t);
        }

        __syncthreads();   // sbuf reused next iteration
    }
}

// ---------------------------------------------------------------------------
extern "C" void kernel_launch(void* const* d_in, const int* in_sizes, int n_in,
                              void* d_out, int out_size) {
    const float* x  = (const float*)d_in[0];
    const float* w1 = (const float*)d_in[1];
    const float* b1 = (const float*)d_in[2];
    const float* w2 = (const float*)d_in[3];
    const float* b2 = (const float*)d_in[4];
    float* out = (float*)d_out;

    const int smem = HW4_ * sizeof(float4);   // 50176 B dynamic
    cudaFuncSetAttribute(se_fused_kernel,
                         cudaFuncAttributeMaxDynamicSharedMemorySize, smem);

    se_fused_kernel<<<C_, T_, smem>>>(x, w1, b1, w2, b2, out);
}

// round 4
// speedup vs baseline: 2.4512x; 2.4512x over previous
#include <cuda_runtime.h>
#include <cuda_bf16.h>
#include <cstdint>

// Problem shape (fixed by reference setup_inputs)
#define B_    16
#define C_    384
#define CR_   96
#define HW_   12544          // 112*112
#define HW4_  3136           // HW/4 (float4 per plane); 3136 = 448*7 exactly
#define T_    448            // threads per CTA
#define K_    7              // float4 chunks per thread

#define CHUNK_B_  4                      // batches per group (4*19.25MB = 77MB < L2)
#define NGROUPS_  (B_ / CHUNK_B_)        // 4
#define GPLANES_  (CHUNK_B_ * C_)        // 1536 CTAs per group kernel

// Scratch (no cudaMalloc allowed) — device globals.
__device__ float g_mean[B_ * C_];
__device__ float g_scale[B_ * C_];

// ---------------------------------------------------------------------------
// Kernel 1: per-plane mean for one 4-batch chunk. Allocating loads so the
// chunk stays L2-resident for the scale kernel that follows.
// ---------------------------------------------------------------------------
__global__ void __launch_bounds__(T_) se_reduce_kernel(const float* __restrict__ x,
                                                       int b0) {
    const int plane = b0 * C_ + blockIdx.x;          // global plane index
    const float4* __restrict__ p =
        reinterpret_cast<const float4*>(x) + (size_t)plane * HW4_;

    float4 v[K_];
    #pragma unroll
    for (int k = 0; k < K_; k++)
        v[k] = p[threadIdx.x + k * T_];              // default: allocate in L2

    float sum = 0.0f;
    #pragma unroll
    for (int k = 0; k < K_; k++)
        sum += (v[k].x + v[k].y) + (v[k].z + v[k].w);

    #pragma unroll
    for (int o = 16; o > 0; o >>= 1)
        sum += __shfl_down_sync(0xffffffffu, sum, o);

    __shared__ float sdata[T_ / 32];                 // 14 warps
    const int lane = threadIdx.x & 31;
    const int wid  = threadIdx.x >> 5;
    if (lane == 0) sdata[wid] = sum;
    __syncthreads();
    if (wid == 0) {
        sum = (lane < (T_ / 32)) ? sdata[lane] : 0.0f;
        #pragma unroll
        for (int o = 8; o > 0; o >>= 1)
            sum += __shfl_down_sync(0xffffffffu, sum, o);
        if (lane == 0) g_mean[plane] = sum * (1.0f / (float)HW_);
    }
}

// ---------------------------------------------------------------------------
// Kernel 2: FC chain for CHUNK_B_ batches. 4 CTAs x 384 threads.
// ---------------------------------------------------------------------------
__global__ void __launch_bounds__(C_) se_fc_kernel(const float* __restrict__ w1,
                                                   const float* __restrict__ b1,
                                                   const float* __restrict__ w2,
                                                   const float* __restrict__ b2,
                                                   int b0) {
    const int b   = b0 + blockIdx.x;
    const int tid = threadIdx.x;

    __shared__ float s[C_];
    __shared__ float t[CR_];

    s[tid] = g_mean[b * C_ + tid];
    __syncthreads();

    if (tid < CR_) {
        float acc = b1[tid];
        const float* __restrict__ wr = w1 + tid * C_;
        #pragma unroll 8
        for (int c = 0; c < C_; c++) acc = fmaf(s[c], wr[c], acc);
        t[tid] = fmaxf(acc, 0.0f);
    }
    __syncthreads();

    float acc = b2[tid];
    const float* __restrict__ wc = w2 + tid * CR_;
    #pragma unroll 8
    for (int r = 0; r < CR_; r++) acc = fmaf(t[r], wc[r], acc);

    g_scale[b * C_ + tid] = __saturatef(fmaf(acc, 1.0f / 6.0f, 0.5f));
}

// ---------------------------------------------------------------------------
// Kernel 3: scale one chunk. Reads should hit L2 (just loaded by reduce);
// __ldcs marks them evict-first after the hit, __stcs keeps the 77MB of
// output from polluting L2.
// ---------------------------------------------------------------------------
__global__ void __launch_bounds__(T_) se_scale_kernel(const float* __restrict__ x,
                                                      float* __restrict__ out,
                                                      int b0) {
    const int plane = b0 * C_ + blockIdx.x;
    const float sc = g_scale[plane];
    const float4* __restrict__ p =
        reinterpret_cast<const float4*>(x) + (size_t)plane * HW4_;
    float4* __restrict__ o =
        reinterpret_cast<float4*>(out) + (size_t)plane * HW4_;

    float4 v[K_];
    #pragma unroll
    for (int k = 0; k < K_; k++)
        v[k] = __ldcs(&p[threadIdx.x + k * T_]);

    #pragma unroll
    for (int k = 0; k < K_; k++) {
        v[k].x *= sc; v[k].y *= sc; v[k].z *= sc; v[k].w *= sc;
        __stcs(&o[threadIdx.x + k * T_], v[k]);
    }
}

// ---------------------------------------------------------------------------
extern "C" void kernel_launch(void* const* d_in, const int* in_sizes, int n_in,
                              void* d_out, int out_size) {
    const float* x  = (const float*)d_in[0];
    const float* w1 = (const float*)d_in[1];
    const float* b1 = (const float*)d_in[2];
    const float* w2 = (const float*)d_in[3];
    const float* b2 = (const float*)d_in[4];
    float* out = (float*)d_out;

    for (int g = 0; g < NGROUPS_; g++) {
        const int b0 = g * CHUNK_B_;
        se_reduce_kernel<<<GPLANES_, T_>>>(x, b0);
        se_fc_kernel<<<CHUNK_B_, C_>>>(w1, b1, w2, b2, b0);
        se_scale_kernel<<<GPLANES_, T_>>>(x, out, b0);
    }
}

// round 5
// speedup vs baseline: 4.1403x; 1.6891x over previous
#include <cuda_runtime.h>
#include <cuda_bf16.h>
#include <cstdint>

// Problem shape (fixed by reference setup_inputs)
#define B_    16
#define C_    384
#define CR_   96
#define HW_   12544          // 112*112
#define HW4_  3136           // HW/4 (float4 per plane)
#define NPLANES_ (B_ * C_)   // 6144

// Reduce kernel tiling: 448 thr x 7 float4 (exact)
#define RT_   448
#define RK_   7

// Scale kernel tiling: 224 thr x 14 float4 (exact) -> MLP 14/thread
#define ST_   224
#define SK_   14
#define SPIPE_ 7             // software pipeline depth (loads in flight)

// Scratch (no cudaMalloc allowed) — device globals.
__device__ float g_mean[NPLANES_];
__device__ float g_scale[NPLANES_];

// ---------------------------------------------------------------------------
// Kernel 1: per-plane mean. One CTA per plane. Already at DRAM roofline.
// Default (allocating) loads leave the tail of x resident in L2 for kernel 3.
// ---------------------------------------------------------------------------
__global__ void __launch_bounds__(RT_) se_reduce_kernel(const float* __restrict__ x) {
    const int plane = blockIdx.x;
    const float4* __restrict__ p =
        reinterpret_cast<const float4*>(x) + (size_t)plane * HW4_;

    float4 v[RK_];
    #pragma unroll
    for (int k = 0; k < RK_; k++)
        v[k] = p[threadIdx.x + k * RT_];

    float sum = 0.0f;
    #pragma unroll
    for (int k = 0; k < RK_; k++)
        sum += (v[k].x + v[k].y) + (v[k].z + v[k].w);

    #pragma unroll
    for (int o = 16; o > 0; o >>= 1)
        sum += __shfl_down_sync(0xffffffffu, sum, o);

    __shared__ float sdata[RT_ / 32];
    const int lane = threadIdx.x & 31;
    const int wid  = threadIdx.x >> 5;
    if (lane == 0) sdata[wid] = sum;
    __syncthreads();
    if (wid == 0) {
        sum = (lane < (RT_ / 32)) ? sdata[lane] : 0.0f;
        #pragma unroll
        for (int o = 8; o > 0; o >>= 1)
            sum += __shfl_down_sync(0xffffffffu, sum, o);
        if (lane == 0) g_mean[plane] = sum * (1.0f / (float)HW_);
    }
}

// ---------------------------------------------------------------------------
// Kernel 2: tiny FC chain per batch. 16 CTAs x 384 threads. ~3us.
// ---------------------------------------------------------------------------
__global__ void __launch_bounds__(C_) se_fc_kernel(const float* __restrict__ w1,
                                                   const float* __restrict__ b1,
                                                   const float* __restrict__ w2,
                                                   const float* __restrict__ b2) {
    const int b   = blockIdx.x;
    const int tid = threadIdx.x;

    __shared__ float s[C_];
    __shared__ float t[CR_];

    s[tid] = g_mean[b * C_ + tid];
    __syncthreads();

    if (tid < CR_) {
        float acc = b1[tid];
        const float* __restrict__ wr = w1 + tid * C_;
        #pragma unroll 8
        for (int c = 0; c < C_; c++) acc = fmaf(s[c], wr[c], acc);
        t[tid] = fmaxf(acc, 0.0f);
    }
    __syncthreads();

    float acc = b2[tid];
    const float* __restrict__ wc = w2 + tid * CR_;
    #pragma unroll 8
    for (int r = 0; r < CR_; r++) acc = fmaf(t[r], wc[r], acc);

    g_scale[b * C_ + tid] = __saturatef(fmaf(acc, 1.0f / 6.0f, 0.5f));
}

// ---------------------------------------------------------------------------
// Kernel 3: broadcast multiply. 224 thr x 14 float4 per plane (exact).
// Software pipeline: 7 loads in flight at all times; stores interleaved so
// the read stream never stalls while writes drain. Reverse plane order to
// reuse the x-tail the reduce kernel left in L2. Streaming (.cs) hints.
// ---------------------------------------------------------------------------
__global__ void __launch_bounds__(ST_) se_scale_kernel(const float* __restrict__ x,
                                                       float* __restrict__ out) {
    const int plane = (NPLANES_ - 1) - blockIdx.x;
    const float sc = g_scale[plane];
    const float4* __restrict__ p =
        reinterpret_cast<const float4*>(x) + (size_t)plane * HW4_;
    float4* __restrict__ o =
        reinterpret_cast<float4*>(out) + (size_t)plane * HW4_;
    const int tid = threadIdx.x;

    float4 v[SK_];

    // Prologue: fill the pipeline with SPIPE_ loads.
    #pragma unroll
    for (int k = 0; k < SPIPE_; k++)
        v[k] = __ldcs(&p[tid + k * ST_]);

    // Steady state: store k, issue load k+SPIPE_.
    #pragma unroll
    for (int k = 0; k < SK_ - SPIPE_; k++) {
        v[k + SPIPE_] = __ldcs(&p[tid + (k + SPIPE_) * ST_]);
        float4 t = v[k];
        t.x *= sc; t.y *= sc; t.z *= sc; t.w *= sc;
        __stcs(&o[tid + k * ST_], t);
    }

    // Epilogue: drain remaining stores.
    #pragma unroll
    for (int k = SK_ - SPIPE_; k < SK_; k++) {
        float4 t = v[k];
        t.x *= sc; t.y *= sc; t.z *= sc; t.w *= sc;
        __stcs(&o[tid + k * ST_], t);
    }
}

// ---------------------------------------------------------------------------
extern "C" void kernel_launch(void* const* d_in, const int* in_sizes, int n_in,
                              void* d_out, int out_size) {
    const float* x  = (const float*)d_in[0];
    const float* w1 = (const float*)d_in[1];
    const float* b1 = (const float*)d_in[2];
    const float* w2 = (const float*)d_in[3];
    const float* b2 = (const float*)d_in[4];
    float* out = (float*)d_out;

    se_reduce_kernel<<<NPLANES_, RT_>>>(x);
    se_fc_kernel<<<B_, C_>>>(w1, b1, w2, b2);
    se_scale_kernel<<<NPLANES_, ST_>>>(x, out);
}